// round 12
// baseline (speedup 1.0000x reference)
#include <cuda_runtime.h>
#include <cstdint>

// WordEmbedding: out[row, :] = W[ids[row], :]
//   W: [50257, 1024] fp32 (4KB rows), ids: [32768] int32, out: [32768,1024] fp32
//
// At the LTS crossbar cap (~256MB through L2 per launch). Persistent
// software-pipelined gather with EXACTLY uniform work split: 1024 CTAs x
// exactly 4 tiles each (tile = bid + k*1024) -- the R11 grid-stride split
// (3 vs 4 tiles/CTA) created a straggler tail that cost 2us of wall time
// per replay despite the best kernel time.

#define DIM 1024
#define VEC_PER_ROW (DIM / 4)   // 256 float4 per row
#define ROWS_PER_TILE 8
#define GRID 1024
#define TILES_PER_CTA 4         // 4096 tiles / 1024 CTAs, exact

__device__ __forceinline__ void load_tile(const float4* __restrict__ w,
                                          const int* __restrict__ ids,
                                          int base_row, int t,
                                          unsigned long long pol_keep,
                                          float4 v[ROWS_PER_TILE])
{
    const int4* ids4 = (const int4*)(ids + base_row);
    const int4 ia = __ldg(&ids4[0]);
    const int4 ib = __ldg(&ids4[1]);
    const int id[ROWS_PER_TILE] = {ia.x, ia.y, ia.z, ia.w, ib.x, ib.y, ib.z, ib.w};
#pragma unroll
    for (int r = 0; r < ROWS_PER_TILE; r++) {
        const float4* p = w + (((size_t)id[r]) << 8) + t;
        asm volatile("ld.global.nc.L2::cache_hint.v4.f32 {%0,%1,%2,%3}, [%4], %5;"
                     : "=f"(v[r].x), "=f"(v[r].y), "=f"(v[r].z), "=f"(v[r].w)
                     : "l"(p), "l"(pol_keep));
    }
}

__device__ __forceinline__ void store_tile(float4* __restrict__ out,
                                           int base_row, int t,
                                           unsigned long long pol_drop,
                                           const float4 v[ROWS_PER_TILE])
{
#pragma unroll
    for (int r = 0; r < ROWS_PER_TILE; r++) {
        float4* q = out + (((size_t)(base_row + r)) << 8) + t;
        asm volatile("st.global.L2::cache_hint.v4.f32 [%0], {%1,%2,%3,%4}, %5;"
                     :: "l"(q), "f"(v[r].x), "f"(v[r].y), "f"(v[r].z), "f"(v[r].w),
                        "l"(pol_drop)
                     : "memory");
    }
}

__global__ __launch_bounds__(256)
void WordEmbedding_43181601194151_kernel(const float4* __restrict__ w,
                                         const int* __restrict__ ids,
                                         float4* __restrict__ out)
{
    const int t = threadIdx.x;

    unsigned long long pol_keep, pol_drop;
    asm("createpolicy.fractional.L2::evict_last.b64  %0, 1.0;" : "=l"(pol_keep));
    asm("createpolicy.fractional.L2::evict_first.b64 %0, 1.0;" : "=l"(pol_drop));

    // Tiles for this CTA: bid, bid+1024, bid+2048, bid+3072 (exactly 4 each).
    float4 va[ROWS_PER_TILE], vb[ROWS_PER_TILE];

    int tile0 = blockIdx.x;
    load_tile(w, ids, tile0 * ROWS_PER_TILE, t, pol_keep, va);

#pragma unroll
    for (int k = 0; k < TILES_PER_CTA; k++) {
        const int cur  = blockIdx.x + k * GRID;
        // Prefetch next tile's gathers before current stores (pipe never drains)
        if (k + 1 < TILES_PER_CTA) {
            const int nxt = blockIdx.x + (k + 1) * GRID;
            if (k & 1) {
                load_tile(w, ids, nxt * ROWS_PER_TILE, t, pol_keep, va);
                store_tile(out, cur * ROWS_PER_TILE, t, pol_drop, vb);
            } else {
                load_tile(w, ids, nxt * ROWS_PER_TILE, t, pol_keep, vb);
                store_tile(out, cur * ROWS_PER_TILE, t, pol_drop, va);
            }
        } else {
            if (k & 1) store_tile(out, cur * ROWS_PER_TILE, t, pol_drop, vb);
            else       store_tile(out, cur * ROWS_PER_TILE, t, pol_drop, va);
        }
    }
}

extern "C" void kernel_launch(void* const* d_in, const int* in_sizes, int n_in,
                              void* d_out, int out_size)
{
    // Select inputs by size: the weight matrix is by far the larger tensor.
    int w_idx = 0, id_idx = 1;
    if (n_in >= 2 && in_sizes[1] > in_sizes[0]) { w_idx = 1; id_idx = 0; }

    const float4* w   = (const float4*)d_in[w_idx];
    const int*    ids = (const int*)d_in[id_idx];
    float4*       out = (float4*)d_out;

    WordEmbedding_43181601194151_kernel<<<GRID, 256>>>(w, ids, out);
}

// round 13
// speedup vs baseline: 1.0974x; 1.0974x over previous
#include <cuda_runtime.h>
#include <cstdint>

// WordEmbedding: out[row, :] = W[ids[row], :]
//   W: [50257, 1024] fp32 (4KB rows), ids: [32768] int32, out: [32768,1024] fp32
//
// Kernel time is pinned at ~36us by the L2/mixed-traffic ceiling (~7.2TB/s
// through LTS); remaining wall-time lever is the completion tail. Finer work
// quanta (4 rows/CTA, 8192 CTAs) smooth the final wave; front-batched loads
// keep MLP=4/thread; L2 hints pin weight rows (evict_last) and stream the
// dead output (evict_first).

#define DIM 1024
#define VEC_PER_ROW (DIM / 4)   // 256 float4 per row
#define ROWS_PER_CTA 4

__global__ __launch_bounds__(256)
void WordEmbedding_43181601194151_kernel(const float4* __restrict__ w,
                                         const int* __restrict__ ids,
                                         float4* __restrict__ out)
{
    const int base_row = blockIdx.x * ROWS_PER_CTA;
    const int t = threadIdx.x;

    unsigned long long pol_keep, pol_drop;
    asm("createpolicy.fractional.L2::evict_last.b64  %0, 1.0;" : "=l"(pol_keep));
    asm("createpolicy.fractional.L2::evict_first.b64 %0, 1.0;" : "=l"(pol_drop));

    // One vectorized id fetch for the CTA's 4 rows.
    const int4 ia = __ldg((const int4*)(ids + base_row));
    const int id[ROWS_PER_CTA] = {ia.x, ia.y, ia.z, ia.w};

    // Front-batched gather loads (4 independent LDG.128 in flight per thread).
    float4 v[ROWS_PER_CTA];
#pragma unroll
    for (int r = 0; r < ROWS_PER_CTA; r++) {
        const float4* p = w + (((size_t)id[r]) << 8) + t;
        asm volatile("ld.global.nc.L2::cache_hint.v4.f32 {%0,%1,%2,%3}, [%4], %5;"
                     : "=f"(v[r].x), "=f"(v[r].y), "=f"(v[r].z), "=f"(v[r].w)
                     : "l"(p), "l"(pol_keep));
    }

    // Streaming stores.
#pragma unroll
    for (int r = 0; r < ROWS_PER_CTA; r++) {
        float4* q = out + (((size_t)(base_row + r)) << 8) + t;
        asm volatile("st.global.L2::cache_hint.v4.f32 [%0], {%1,%2,%3,%4}, %5;"
                     :: "l"(q), "f"(v[r].x), "f"(v[r].y), "f"(v[r].z), "f"(v[r].w),
                        "l"(pol_drop)
                     : "memory");
    }
}

extern "C" void kernel_launch(void* const* d_in, const int* in_sizes, int n_in,
                              void* d_out, int out_size)
{
    // Select inputs by size: the weight matrix is by far the larger tensor.
    int w_idx = 0, id_idx = 1;
    if (n_in >= 2 && in_sizes[1] > in_sizes[0]) { w_idx = 1; id_idx = 0; }

    const float4* w   = (const float4*)d_in[w_idx];
    const int*    ids = (const int*)d_in[id_idx];
    float4*       out = (float4*)d_out;

    const int n_rows   = out_size / DIM;             // 32768
    const int n_blocks = n_rows / ROWS_PER_CTA;      // 8192

    WordEmbedding_43181601194151_kernel<<<n_blocks, 256>>>(w, ids, out);
}